// round 16
// baseline (speedup 1.0000x reference)
#include <cuda_runtime.h>
#include <cuda_bf16.h>
#include <cstdint>

#define B_    8
#define C_    1024
#define T_    1500
#define M_    (B_*T_)
#define KC_   8192
#define D_    256
#define H_    512
#define NQ_   4
#define BINS_ 1024
#define LRELU_SLOPE 0.01f
#define EPS_  1e-8f
#define MARGIN_ 64.0f

// rvq_all smem layout (bytes)
#define RVQ_AS_SZ   (256*136*4)
#define RVQ_BS_SZ   (2*16*136*4)
#define RVQ_BEST_SZ (128*8)
#define RVQ_E_SZ    (128*4)
#define RVQ_SM_TOTAL (RVQ_AS_SZ + RVQ_BS_SZ + RVQ_BEST_SZ + RVQ_E_SZ)

__device__ __align__(16) float g_x   [M_*C_];
__device__ __align__(16) float g_lin [M_*C_];
__device__ __align__(16) float g_raw [M_*C_];
__device__ __align__(16) float g_obt [M_*C_];
__device__ __align__(16) float g_h0  [M_*H_];
__device__ __align__(16) float g_h1  [M_*H_];
__device__ __align__(16) float g_h0b [M_*H_];
__device__ __align__(16) float g_h1b [M_*H_];
__device__ __align__(16) float g_spk [M_*D_];
__device__ __align__(16) float g_nrm [M_*D_];
__device__ __align__(16) float g_sen [M_*D_];
__device__ __align__(16) float g_res [M_*D_];
__device__ __align__(16) float g_qs  [M_*D_];
__device__ __align__(16) float g_den [M_*D_];
__device__ float g_cnorm[KC_];
__device__ float g_bnorm[NQ_*BINS_];
__device__ float g_E[M_];
__device__ unsigned long long g_mk[M_];
__device__ __align__(16) __nv_bfloat16 g_xb[M_*C_];
__device__ __align__(16) __nv_bfloat16 g_cb[KC_*C_];
__device__ __align__(16) __nv_bfloat16 g_adist[(size_t)M_*KC_];
__device__ unsigned int g_amin[M_];

__device__ __forceinline__ unsigned int f2key(float f) {
    unsigned int u = __float_as_uint(f);
    return (u & 0x80000000u) ? ~u : (u | 0x80000000u);
}
__device__ __forceinline__ float key2f(unsigned int u) {
    return (u & 0x80000000u) ? __uint_as_float(u ^ 0x80000000u)
                             : __uint_as_float(~u);
}
__device__ __forceinline__ float tf32r(float v) {
    unsigned u;
    asm("cvt.rna.tf32.f32 %0, %1;" : "=r"(u) : "f"(v));
    return __uint_as_float(u);
}

__device__ __forceinline__ void mma16816(float* c, const unsigned* a, const unsigned* b) {
    asm volatile(
        "mma.sync.aligned.m16n8k16.row.col.f32.bf16.bf16.f32 "
        "{%0,%1,%2,%3}, {%4,%5,%6,%7}, {%8,%9}, {%0,%1,%2,%3};\n"
        : "+f"(c[0]), "+f"(c[1]), "+f"(c[2]), "+f"(c[3])
        : "r"(a[0]), "r"(a[1]), "r"(a[2]), "r"(a[3]), "r"(b[0]), "r"(b[1]));
}
__device__ __forceinline__ void mma_tf32(float* c, const unsigned* a, const unsigned* b) {
    asm volatile(
        "mma.sync.aligned.m16n8k8.row.col.f32.tf32.tf32.f32 "
        "{%0,%1,%2,%3}, {%4,%5,%6,%7}, {%8,%9}, {%0,%1,%2,%3};\n"
        : "+f"(c[0]), "+f"(c[1]), "+f"(c[2]), "+f"(c[3])
        : "r"(a[0]), "r"(a[1]), "r"(a[2]), "r"(a[3]), "r"(b[0]), "r"(b[1]));
}
__device__ __forceinline__ void ldsm_x4(unsigned& r0, unsigned& r1,
                                        unsigned& r2, unsigned& r3, unsigned addr) {
    asm volatile("ldmatrix.sync.aligned.m8n8.x4.shared.b16 {%0,%1,%2,%3}, [%4];"
                 : "=r"(r0), "=r"(r1), "=r"(r2), "=r"(r3) : "r"(addr));
}

// ---- coalesced row sum-of-squares ----------------------------------------
__global__ void row_sumsq_warp(const float* __restrict__ rows, float* __restrict__ out,
                               int R, int L) {
    int w = (blockIdx.x * blockDim.x + threadIdx.x) >> 5;
    int lane = threadIdx.x & 31;
    int half = lane >> 4, l = lane & 15;
    int r = w * 2 + half;
    float p = 0.f;
    if (r < R) {
        const float* base = rows + (size_t)r * L + l;
        for (int j = 0; j < L; j += 16) {
            float v = __ldg(base + j);
            p = __fmaf_rn(v, v, p);
        }
    }
    float t = __shfl_xor_sync(0xffffffffu, p, 4);
    float q = __fadd_rn(p, t);
    t = __shfl_xor_sync(0xffffffffu, q, 8);
    float c = __fadd_rn(q, t);
    t = __shfl_xor_sync(0xffffffffu, c, 1);
    float u = __fadd_rn(c, t);
    t = __shfl_xor_sync(0xffffffffu, u, 2);
    float s = __fadd_rn(u, t);
    if (l == 0 && r < R) out[r] = s;
}

__global__ void reset_amin() {
    int i = blockIdx.x * blockDim.x + threadIdx.x;
    if (i < M_) g_amin[i] = 0xFFFFFFFFu;
}

__global__ void to_bf16(const float* __restrict__ in, __nv_bfloat16* __restrict__ out,
                        int n) {
    int i = blockIdx.x * blockDim.x + threadIdx.x;
    if (i * 2 + 1 < n) {
        float2 v = ((const float2*)in)[i];
        ((__nv_bfloat162*)out)[i] = __nv_bfloat162(__float2bfloat16(v.x),
                                                   __float2bfloat16(v.y));
    }
}

// fused: (B,C,T)->(B*T,C) transpose + bf16 copy of x
__global__ void transpose_in(const float* __restrict__ f, float* __restrict__ x,
                             __nv_bfloat16* __restrict__ xb) {
    __shared__ float tile[32][33];
    int b = blockIdx.z, t0 = blockIdx.x * 32, c0 = blockIdx.y * 32;
    int tx = threadIdx.x, ty = threadIdx.y;
    #pragma unroll
    for (int i = 0; i < 32; i += 8) {
        int cc = c0 + ty + i, t = t0 + tx;
        if (t < T_ && cc < C_) tile[ty + i][tx] = f[((size_t)b * C_ + cc) * T_ + t];
    }
    __syncthreads();
    #pragma unroll
    for (int i = 0; i < 32; i += 8) {
        int tt = t0 + ty + i, cc = c0 + tx;
        if (tt < T_ && cc < C_) {
            float v = tile[tx][ty + i];
            size_t o = ((size_t)b * T_ + tt) * C_ + cc;
            x[o] = v;
            xb[o] = __float2bfloat16(v);
        }
    }
}

__global__ void transpose_out(const float* __restrict__ x, float* __restrict__ f) {
    __shared__ float tile[32][33];
    int b = blockIdx.z, t0 = blockIdx.x * 32, c0 = blockIdx.y * 32;
    int tx = threadIdx.x, ty = threadIdx.y;
    #pragma unroll
    for (int i = 0; i < 32; i += 8) {
        int tt = t0 + ty + i, cc = c0 + tx;
        if (tt < T_ && cc < C_) tile[ty + i][tx] = x[((size_t)b * T_ + tt) * C_ + cc];
    }
    __syncthreads();
    #pragma unroll
    for (int i = 0; i < 32; i += 8) {
        int cc = c0 + ty + i, t = t0 + tx;
        if (t < T_ && cc < C_) f[((size_t)b * C_ + cc) * T_ + t] = tile[tx][ty + i];
    }
}

// ---- PASS 1: bf16 mma.sync approx distances (linguistic) ------------------
__global__ __launch_bounds__(256)
void vq_approx(const __nv_bfloat16* __restrict__ xb,
               const __nv_bfloat16* __restrict__ cb,
               const float* __restrict__ G) {
    __shared__ __nv_bfloat16 a_sm[2][128][40];
    __shared__ __nv_bfloat16 b_sm[2][128][40];
    const unsigned PITCHB = 80, BUFB = 128 * 80;
    int tid = threadIdx.x;
    int m0 = blockIdx.y * 128, n0 = blockIdx.x * 128;
    int w = tid >> 5, lane = tid & 31;
    int wm = w & 1, wn = w >> 1;
    float acc[4][4][4];
    #pragma unroll
    for (int a = 0; a < 4; a++)
        #pragma unroll
        for (int b = 0; b < 4; b++)
            #pragma unroll
            for (int q = 0; q < 4; q++) acc[a][b][q] = 0.f;

    unsigned aBase = (unsigned)__cvta_generic_to_shared(&a_sm[0][0][0]);
    unsigned bBase = (unsigned)__cvta_generic_to_shared(&b_sm[0][0][0]);
    int i8 = lane & 7, tt = lane >> 3;
    unsigned aRow = (tt & 1) * 8 + i8, aCol = (tt >> 1) * 16;
    unsigned bRow = (tt >> 1) * 8 + i8, bCol = (tt & 1) * 16;

    int row0 = tid >> 2, cg0 = tid & 3;
    int row1 = (tid + 256) >> 2, cg1 = tid & 3;
    int gm0 = m0 + row0, gm1 = m0 + row1;

    float4 pa0 = make_float4(0.f,0.f,0.f,0.f), pa1 = make_float4(0.f,0.f,0.f,0.f);
    float4 pb0, pb1;
    if (gm0 < M_) pa0 = *(const float4*)(xb + (size_t)gm0 * C_ + cg0 * 8);
    if (gm1 < M_) pa1 = *(const float4*)(xb + (size_t)gm1 * C_ + cg1 * 8);
    pb0 = *(const float4*)(cb + (size_t)(n0 + row0) * C_ + cg0 * 8);
    pb1 = *(const float4*)(cb + (size_t)(n0 + row1) * C_ + cg1 * 8);
    *(float4*)&a_sm[0][row0][cg0 * 8] = pa0;
    *(float4*)&a_sm[0][row1][cg1 * 8] = pa1;
    *(float4*)&b_sm[0][row0][cg0 * 8] = pb0;
    *(float4*)&b_sm[0][row1][cg1 * 8] = pb1;
    __syncthreads();

    int buf = 0;
    for (int k0 = 0; k0 < C_; k0 += 32) {
        bool hn = (k0 + 32) < C_;
        if (hn) {
            int kn = k0 + 32;
            pa0 = make_float4(0.f,0.f,0.f,0.f); pa1 = make_float4(0.f,0.f,0.f,0.f);
            if (gm0 < M_) pa0 = *(const float4*)(xb + (size_t)gm0 * C_ + kn + cg0 * 8);
            if (gm1 < M_) pa1 = *(const float4*)(xb + (size_t)gm1 * C_ + kn + cg1 * 8);
            pb0 = *(const float4*)(cb + (size_t)(n0 + row0) * C_ + kn + cg0 * 8);
            pb1 = *(const float4*)(cb + (size_t)(n0 + row1) * C_ + kn + cg1 * 8);
        }
        unsigned bufOff = buf * BUFB;
        #pragma unroll
        for (int kk = 0; kk < 32; kk += 16) {
            unsigned a[4][4], b[4][2];
            #pragma unroll
            for (int mf = 0; mf < 4; mf++) {
                unsigned ad = aBase + bufOff +
                              (unsigned)(wm * 64 + mf * 16 + aRow) * PITCHB + aCol + kk * 2;
                ldsm_x4(a[mf][0], a[mf][1], a[mf][2], a[mf][3], ad);
            }
            #pragma unroll
            for (int p = 0; p < 2; p++) {
                unsigned bd = bBase + bufOff +
                              (unsigned)(wn * 32 + p * 16 + bRow) * PITCHB + bCol + kk * 2;
                unsigned r0, r1, r2, r3;
                ldsm_x4(r0, r1, r2, r3, bd);
                b[2 * p][0] = r0; b[2 * p][1] = r1;
                b[2 * p + 1][0] = r2; b[2 * p + 1][1] = r3;
            }
            #pragma unroll
            for (int mf = 0; mf < 4; mf++)
                #pragma unroll
                for (int nf = 0; nf < 4; nf++)
                    mma16816(acc[mf][nf], a[mf], b[nf]);
        }
        if (hn) {
            int nb = buf ^ 1;
            *(float4*)&a_sm[nb][row0][cg0 * 8] = pa0;
            *(float4*)&a_sm[nb][row1][cg1 * 8] = pa1;
            *(float4*)&b_sm[nb][row0][cg0 * 8] = pb0;
            *(float4*)&b_sm[nb][row1][cg1 * 8] = pb1;
        }
        __syncthreads();
        buf ^= 1;
    }
    int r = lane >> 2, c2 = (lane & 3) * 2;
    #pragma unroll
    for (int mf = 0; mf < 4; mf++) {
        int ro0 = m0 + wm * 64 + mf * 16 + r;
        int ro1 = ro0 + 8;
        float mn0 = 3.4e38f, mn1 = 3.4e38f;
        #pragma unroll
        for (int nf = 0; nf < 4; nf++) {
            int col = n0 + wn * 32 + nf * 8 + c2;
            float gv0 = G[col], gv1 = G[col + 1];
            __nv_bfloat16 h00 = __float2bfloat16(gv0 - 2.f * acc[mf][nf][0]);
            __nv_bfloat16 h01 = __float2bfloat16(gv1 - 2.f * acc[mf][nf][1]);
            __nv_bfloat16 h10 = __float2bfloat16(gv0 - 2.f * acc[mf][nf][2]);
            __nv_bfloat16 h11 = __float2bfloat16(gv1 - 2.f * acc[mf][nf][3]);
            if (ro0 < M_)
                *(__nv_bfloat162*)&g_adist[(size_t)ro0 * KC_ + col] = __nv_bfloat162(h00, h01);
            if (ro1 < M_)
                *(__nv_bfloat162*)&g_adist[(size_t)ro1 * KC_ + col] = __nv_bfloat162(h10, h11);
            mn0 = fminf(mn0, fminf(__bfloat162float(h00), __bfloat162float(h01)));
            mn1 = fminf(mn1, fminf(__bfloat162float(h10), __bfloat162float(h11)));
        }
        #pragma unroll
        for (int o = 1; o < 4; o <<= 1) {
            mn0 = fminf(mn0, __shfl_xor_sync(0xffffffffu, mn0, o));
            mn1 = fminf(mn1, __shfl_xor_sync(0xffffffffu, mn1, o));
        }
        if ((lane & 3) == 0) {
            if (ro0 < M_) atomicMin(&g_amin[ro0], f2key(mn0));
            if (ro1 < M_) atomicMin(&g_amin[ro1], f2key(mn1));
        }
    }
}

// ---- PASS 2: exact re-evaluation of candidates + fused gather/sub ---------
__global__ __launch_bounds__(256)
void vq_exact(const float* __restrict__ cent) {
    __shared__ float xs[8][1024];
    __shared__ int cands[8][256];
    __shared__ int cnt[8];
    int w = threadIdx.x >> 5, lane = threadIdx.x & 31;
    int m0 = blockIdx.x * 8;
    #pragma unroll
    for (int r = 0; r < 8; r++) {
        int m = m0 + r;
        if (m < M_)
            ((float4*)xs[r])[threadIdx.x] = ((const float4*)(g_x + (size_t)m * C_))[threadIdx.x];
    }
    if (lane == 0) cnt[w] = 0;
    __syncthreads();
    int m = m0 + w;
    if (m >= M_) return;
    float thr = key2f(g_amin[m]) + MARGIN_;
    const __nv_bfloat16* drow = g_adist + (size_t)m * KC_;
    for (int base = 0; base < KC_; base += 256) {
        int n0c = base + lane * 8;
        uint4 vv = *(const uint4*)(drow + n0c);
        const __nv_bfloat162* hp = (const __nv_bfloat162*)&vv;
        #pragma unroll
        for (int q = 0; q < 4; q++) {
            if (__bfloat162float(hp[q].x) <= thr) {
                int p = atomicAdd(&cnt[w], 1);
                if (p < 256) cands[w][p] = n0c + q * 2;
            }
            if (__bfloat162float(hp[q].y) <= thr) {
                int p = atomicAdd(&cnt[w], 1);
                if (p < 256) cands[w][p] = n0c + q * 2 + 1;
            }
        }
    }
    __syncwarp();
    int nc = cnt[w]; if (nc > 256) nc = 256;
    float E = g_E[m];
    unsigned long long best = ~0ull;
    for (int base = 0; base < nc; base += 32) {
        int li = base + lane;
        unsigned long long pk = ~0ull;
        if (li < nc) {
            int n = cands[w][li];
            const float* c = cent + (size_t)n * C_;
            float F = 0.f;
            for (int k = 0; k < C_; k += 4) {
                float4 cv = __ldg((const float4*)(c + k));
                F = __fmaf_rn(xs[w][k],     cv.x, F);
                F = __fmaf_rn(xs[w][k + 1], cv.y, F);
                F = __fmaf_rn(xs[w][k + 2], cv.z, F);
                F = __fmaf_rn(xs[w][k + 3], cv.w, F);
            }
            float t1 = __fmul_rn(2.0f, F);
            float t2 = __fadd_rn(E, -t1);
            float s  = __fadd_rn(t2, g_cnorm[n]);
            pk = ((unsigned long long)f2key(s) << 32) | (unsigned)n;
        }
        #pragma unroll
        for (int o = 16; o; o >>= 1) {
            unsigned long long ot = __shfl_xor_sync(0xffffffffu, pk, o);
            pk = ot < pk ? ot : pk;
        }
        best = pk < best ? pk : best;
    }
    if (lane == 0) g_mk[m] = best;
    int idx = (int)(best & 0xffffffffu);
    const float* crow = cent + (size_t)idx * C_;
    for (int k = lane * 4; k < C_; k += 128) {
        float4 cv = __ldg((const float4*)(crow + k));
        float4 xv = *(const float4*)&xs[w][k];
        *(float4*)(g_lin + (size_t)m * C_ + k) = cv;
        float4 rv = make_float4(__fadd_rn(xv.x, -cv.x), __fadd_rn(xv.y, -cv.y),
                                __fadd_rn(xv.z, -cv.z), __fadd_rn(xv.w, -cv.w));
        *(float4*)(g_raw + (size_t)m * C_ + k) = rv;
    }
}

// ---- TF32 GEMM + bias + act (+ add), BK=16 --------------------------------
template <int ACT, bool ADD>
__global__ __launch_bounds__(256)
void gemm_tf32(const float* __restrict__ A, const float* __restrict__ W,
               const float* __restrict__ bias, const float* __restrict__ addin,
               float* __restrict__ Cp, int M, int N, int K) {
    __shared__ float As[2][16][136];
    __shared__ float Ws[2][16][136];
    int tid = threadIdx.x;
    int m0 = blockIdx.y * 128, n0 = blockIdx.x * 128;
    int w = tid >> 5, lane = tid & 31;
    int wm = w & 1, wn = w >> 1;
    int g = lane >> 2, t4 = lane & 3;
    int lr = tid >> 1, kb = (tid & 1) * 8;
    int wk = tid >> 4, wnl = (tid & 15) * 8;
    int gm = m0 + lr;
    float acc[4][4][4];
    #pragma unroll
    for (int a = 0; a < 4; a++)
        #pragma unroll
        for (int b = 0; b < 4; b++)
            #pragma unroll
            for (int q = 0; q < 4; q++) acc[a][b][q] = 0.f;

    float4 pa0 = make_float4(0.f,0.f,0.f,0.f), pa1 = pa0;
    if (gm < M) {
        pa0 = *(const float4*)(A + (size_t)gm * K + kb);
        pa1 = *(const float4*)(A + (size_t)gm * K + kb + 4);
    }
    float4 pw0 = *(const float4*)(W + (size_t)wk * N + n0 + wnl);
    float4 pw1 = *(const float4*)(W + (size_t)wk * N + n0 + wnl + 4);
    As[0][kb][lr] = tf32r(pa0.x); As[0][kb+1][lr] = tf32r(pa0.y);
    As[0][kb+2][lr] = tf32r(pa0.z); As[0][kb+3][lr] = tf32r(pa0.w);
    As[0][kb+4][lr] = tf32r(pa1.x); As[0][kb+5][lr] = tf32r(pa1.y);
    As[0][kb+6][lr] = tf32r(pa1.z); As[0][kb+7][lr] = tf32r(pa1.w);
    Ws[0][wk][wnl] = tf32r(pw0.x); Ws[0][wk][wnl+1] = tf32r(pw0.y);
    Ws[0][wk][wnl+2] = tf32r(pw0.z); Ws[0][wk][wnl+3] = tf32r(pw0.w);
    Ws[0][wk][wnl+4] = tf32r(pw1.x); Ws[0][wk][wnl+5] = tf32r(pw1.y);
    Ws[0][wk][wnl+6] = tf32r(pw1.z); Ws[0][wk][wnl+7] = tf32r(pw1.w);
    __syncthreads();

    int buf = 0;
    for (int k0 = 0; k0 < K; k0 += 16) {
        bool hn = (k0 + 16) < K;
        if (hn) {
            int kn = k0 + 16;
            pa0 = make_float4(0.f,0.f,0.f,0.f); pa1 = pa0;
            if (gm < M) {
                pa0 = *(const float4*)(A + (size_t)gm * K + kn + kb);
                pa1 = *(const float4*)(A + (size_t)gm * K + kn + kb + 4);
            }
            pw0 = *(const float4*)(W + (size_t)(kn + wk) * N + n0 + wnl);
            pw1 = *(const float4*)(W + (size_t)(kn + wk) * N + n0 + wnl + 4);
        }
        #pragma unroll
        for (int g2 = 0; g2 < 2; g2++) {
            int ka = t4 + g2 * 8, kc = t4 + 4 + g2 * 8;
            unsigned a[4][4], b[4][2];
            #pragma unroll
            for (int mf = 0; mf < 4; mf++) {
                int mb = wm * 64 + mf * 16 + g;
                a[mf][0] = __float_as_uint(As[buf][ka][mb]);
                a[mf][1] = __float_as_uint(As[buf][ka][mb + 8]);
                a[mf][2] = __float_as_uint(As[buf][kc][mb]);
                a[mf][3] = __float_as_uint(As[buf][kc][mb + 8]);
            }
            #pragma unroll
            for (int nf = 0; nf < 4; nf++) {
                int nb = wn * 32 + nf * 8 + g;
                b[nf][0] = __float_as_uint(Ws[buf][ka][nb]);
                b[nf][1] = __float_as_uint(Ws[buf][kc][nb]);
            }
            #pragma unroll
            for (int mf = 0; mf < 4; mf++)
                #pragma unroll
                for (int nf = 0; nf < 4; nf++)
                    mma_tf32(acc[mf][nf], a[mf], b[nf]);
        }
        if (hn) {
            int nb2 = buf ^ 1;
            As[nb2][kb][lr] = tf32r(pa0.x); As[nb2][kb+1][lr] = tf32r(pa0.y);
            As[nb2][kb+2][lr] = tf32r(pa0.z); As[nb2][kb+3][lr] = tf32r(pa0.w);
            As[nb2][kb+4][lr] = tf32r(pa1.x); As[nb2][kb+5][lr] = tf32r(pa1.y);
            As[nb2][kb+6][lr] = tf32r(pa1.z); As[nb2][kb+7][lr] = tf32r(pa1.w);
            Ws[nb2][wk][wnl] = tf32r(pw0.x); Ws[nb2][wk][wnl+1] = tf32r(pw0.y);
            Ws[nb2][wk][wnl+2] = tf32r(pw0.z); Ws[nb2][wk][wnl+3] = tf32r(pw0.w);
            Ws[nb2][wk][wnl+4] = tf32r(pw1.x); Ws[nb2][wk][wnl+5] = tf32r(pw1.y);
            Ws[nb2][wk][wnl+6] = tf32r(pw1.z); Ws[nb2][wk][wnl+7] = tf32r(pw1.w);
        }
        __syncthreads();
        buf ^= 1;
    }
    #pragma unroll
    for (int mf = 0; mf < 4; mf++) {
        int ro0 = m0 + wm * 64 + mf * 16 + g;
        int ro1 = ro0 + 8;
        #pragma unroll
        for (int nf = 0; nf < 4; nf++) {
            int col = n0 + wn * 32 + nf * 8 + 2 * t4;
            float b0 = bias[col], b1 = bias[col + 1];
            float v00 = acc[mf][nf][0] + b0, v01 = acc[mf][nf][1] + b1;
            float v10 = acc[mf][nf][2] + b0, v11 = acc[mf][nf][3] + b1;
            if (ACT == 1) {
                v00 = (v00 >= 0.f) ? v00 : LRELU_SLOPE * v00;
                v01 = (v01 >= 0.f) ? v01 : LRELU_SLOPE * v01;
                v10 = (v10 >= 0.f) ? v10 : LRELU_SLOPE * v10;
                v11 = (v11 >= 0.f) ? v11 : LRELU_SLOPE * v11;
            } else if (ACT == 2) {
                v00 = fmaxf(v00, 0.f); v01 = fmaxf(v01, 0.f);
                v10 = fmaxf(v10, 0.f); v11 = fmaxf(v11, 0.f);
            }
            if (ro0 < M) {
                float2 o = make_float2(v00, v01);
                if (ADD) {
                    float2 ad = *(const float2*)(addin + (size_t)ro0 * N + col);
                    o.x += ad.x; o.y += ad.y;
                }
                *(float2*)(Cp + (size_t)ro0 * N + col) = o;
            }
            if (ro1 < M) {
                float2 o = make_float2(v10, v11);
                if (ADD) {
                    float2 ad = *(const float2*)(addin + (size_t)ro1 * N + col);
                    o.x += ad.x; o.y += ad.y;
                }
                *(float2*)(Cp + (size_t)ro1 * N + col) = o;
            }
        }
    }
}

// ---- dual-chain TF32 GEMM (enc || nrm), BK=16 -----------------------------
template <int ACTA, int ACTB>
__global__ __launch_bounds__(256)
void gemm_tf32_dual(const float* __restrict__ A0, const float* __restrict__ A1,
                    const float* __restrict__ W0, const float* __restrict__ W1,
                    const float* __restrict__ b0, const float* __restrict__ b1,
                    float* __restrict__ C0, float* __restrict__ C1,
                    int M, int N, int K) {
    const float* A = blockIdx.z ? A1 : A0;
    const float* W = blockIdx.z ? W1 : W0;
    const float* bias = blockIdx.z ? b1 : b0;
    float* Cp = blockIdx.z ? C1 : C0;
    __shared__ float As[2][16][136];
    __shared__ float Ws[2][16][136];
    int tid = threadIdx.x;
    int m0 = blockIdx.y * 128, n0 = blockIdx.x * 128;
    int w = tid >> 5, lane = tid & 31;
    int wm = w & 1, wn = w >> 1;
    int g = lane >> 2, t4 = lane & 3;
    int lr = tid >> 1, kb = (tid & 1) * 8;
    int wk = tid >> 4, wnl = (tid & 15) * 8;
    int gm = m0 + lr;
    float acc[4][4][4];
    #pragma unroll
    for (int a = 0; a < 4; a++)
        #pragma unroll
        for (int b = 0; b < 4; b++)
            #pragma unroll
            for (int q = 0; q < 4; q++) acc[a][b][q] = 0.f;

    float4 pa0 = make_float4(0.f,0.f,0.f,0.f), pa1 = pa0;
    if (gm < M) {
        pa0 = *(const float4*)(A + (size_t)gm * K + kb);
        pa1 = *(const float4*)(A + (size_t)gm * K + kb + 4);
    }
    float4 pw0 = *(const float4*)(W + (size_t)wk * N + n0 + wnl);
    float4 pw1 = *(const float4*)(W + (size_t)wk * N + n0 + wnl + 4);
    As[0][kb][lr] = tf32r(pa0.x); As[0][kb+1][lr] = tf32r(pa0.y);
    As[0][kb+2][lr] = tf32r(pa0.z); As[0][kb+3][lr] = tf32r(pa0.w);
    As[0][kb+4][lr] = tf32r(pa1.x); As[0][kb+5][lr] = tf32r(pa1.y);
    As[0][kb+6][lr] = tf32r(pa1.z); As[0][kb+7][lr] = tf32r(pa1.w);
    Ws[0][wk][wnl] = tf32r(pw0.x); Ws[0][wk][wnl+1] = tf32r(pw0.y);
    Ws[0][wk][wnl+2] = tf32r(pw0.z); Ws[0][wk][wnl+3] = tf32r(pw0.w);
    Ws[0][wk][wnl+4] = tf32r(pw1.x); Ws[0][wk][wnl+5] = tf32r(pw1.y);
    Ws[0][wk][wnl+6] = tf32r(pw1.z); Ws[0][wk][wnl+7] = tf32r(pw1.w);
    __syncthreads();

    int buf = 0;
    for (int k0 = 0; k0 < K; k0 += 16) {
        bool hn = (k0 + 16) < K;
        if (hn) {
            int kn = k0 + 16;
            pa0 = make_float4(0.f,0.f,0.f,0.f); pa1 = pa0;
            if (gm < M) {
                pa0 = *(const float4*)(A + (size_t)gm * K + kn + kb);
                pa1 = *(const float4*)(A + (size_t)gm * K + kn + kb + 4);
            }
            pw0 = *(const float4*)(W + (size_t)(kn + wk) * N + n0 + wnl);
            pw1 = *(const float4*)(W + (size_t)(kn + wk) * N + n0 + wnl + 4);
        }
        #pragma unroll
        for (int g2 = 0; g2 < 2; g2++) {
            int ka = t4 + g2 * 8, kc = t4 + 4 + g2 * 8;
            unsigned a[4][4], b[4][2];
            #pragma unroll
            for (int mf = 0; mf < 4; mf++) {
                int mb = wm * 64 + mf * 16 + g;
                a[mf][0] = __float_as_uint(As[buf][ka][mb]);
                a[mf][1] = __float_as_uint(As[buf][ka][mb + 8]);
                a[mf][2] = __float_as_uint(As[buf][kc][mb]);
                a[mf][3] = __float_as_uint(As[buf][kc][mb + 8]);
            }
            #pragma unroll
            for (int nf = 0; nf < 4; nf++) {
                int nb = wn * 32 + nf * 8 + g;
                b[nf][0] = __float_as_uint(Ws[buf][ka][nb]);
                b[nf][1] = __float_as_uint(Ws[buf][kc][nb]);
            }
            #pragma unroll
            for (int mf = 0; mf < 4; mf++)
                #pragma unroll
                for (int nf = 0; nf < 4; nf++)
                    mma_tf32(acc[mf][nf], a[mf], b[nf]);
        }
        if (hn) {
            int nb2 = buf ^ 1;
            As[nb2][kb][lr] = tf32r(pa0.x); As[nb2][kb+1][lr] = tf32r(pa0.y);
            As[nb2][kb+2][lr] = tf32r(pa0.z); As[nb2][kb+3][lr] = tf32r(pa0.w);
            As[nb2][kb+4][lr] = tf32r(pa1.x); As[nb2][kb+5][lr] = tf32r(pa1.y);
            As[nb2][kb+6][lr] = tf32r(pa1.z); As[nb2][kb+7][lr] = tf32r(pa1.w);
            Ws[nb2][wk][wnl] = tf32r(pw0.x); Ws[nb2][wk][wnl+1] = tf32r(pw0.y);
            Ws[nb2][wk][wnl+2] = tf32r(pw0.z); Ws[nb2][wk][wnl+3] = tf32r(pw0.w);
            Ws[nb2][wk][wnl+4] = tf32r(pw1.x); Ws[nb2][wk][wnl+5] = tf32r(pw1.y);
            Ws[nb2][wk][wnl+6] = tf32r(pw1.z); Ws[nb2][wk][wnl+7] = tf32r(pw1.w);
        }
        __syncthreads();
        buf ^= 1;
    }
    int ACT = blockIdx.z ? ACTB : ACTA;
    #pragma unroll
    for (int mf = 0; mf < 4; mf++) {
        int ro0 = m0 + wm * 64 + mf * 16 + g;
        int ro1 = ro0 + 8;
        #pragma unroll
        for (int nf = 0; nf < 4; nf++) {
            int col = n0 + wn * 32 + nf * 8 + 2 * t4;
            float b0 = bias[col], b1 = bias[col + 1];
            float v00 = acc[mf][nf][0] + b0, v01 = acc[mf][nf][1] + b1;
            float v10 = acc[mf][nf][2] + b0, v11 = acc[mf][nf][3] + b1;
            if (ACT == 1) {
                v00 = (v00 >= 0.f) ? v00 : LRELU_SLOPE * v00;
                v01 = (v01 >= 0.f) ? v01 : LRELU_SLOPE * v01;
                v10 = (v10 >= 0.f) ? v10 : LRELU_SLOPE * v10;
                v11 = (v11 >= 0.f) ? v11 : LRELU_SLOPE * v11;
            } else if (ACT == 2) {
                v00 = fmaxf(v00, 0.f); v01 = fmaxf(v01, 0.f);
                v10 = fmaxf(v10, 0.f); v11 = fmaxf(v11, 0.f);
            }
            if (ro0 < M) *(float2*)(Cp + (size_t)ro0 * N + col) = make_float2(v00, v01);
            if (ro1 < M) *(float2*)(Cp + (size_t)ro1 * N + col) = make_float2(v10, v11);
        }
    }
}

// ---- persistent fused RVQ: init + 4x(argmin+update) + denorm --------------
// One CTA owns 128 rows. Rounded residual lives in smem As[256k][136];
// exact res/qs maintained in gmem (same ops as before -> same numerics).
__global__ __launch_bounds__(256)
void rvq_all(const float* __restrict__ cbs, const float* __restrict__ bnorm) {
    extern __shared__ char smraw[];
    float* As = (float*)smraw;                                   // [256][136]
    float* Bs = (float*)(smraw + RVQ_AS_SZ);                     // [2][16][136]
    unsigned long long* sBest =
        (unsigned long long*)(smraw + RVQ_AS_SZ + RVQ_BS_SZ);    // [128]
    float* sE = (float*)(smraw + RVQ_AS_SZ + RVQ_BS_SZ + RVQ_BEST_SZ);  // [128]

    int tid = threadIdx.x;
    int m0 = blockIdx.x * 128;
    int w = tid >> 5, lane = tid & 31;
    int wm = w & 1, wn = w >> 1;
    int g = lane >> 2, t4 = lane & 3;
    int r16 = tid >> 4, l16 = tid & 15;

    // ---- init: sen = spk/(nrm+eps); res=sen; qs=0; As=tf32r; E ----
    for (int pass = 0; pass < 8; pass++) {
        int row = pass * 16 + r16;
        int m = m0 + row;
        float p = 0.f;
        if (m < M_) {
            size_t base = (size_t)m * D_;
            #pragma unroll
            for (int j = 0; j < 16; j++) {
                int e = j * 16 + l16;
                float se = g_spk[base + e], nv = g_nrm[base + e];
                float r = __fdiv_rn(se, __fadd_rn(nv, EPS_));
                g_sen[base + e] = r;
                g_res[base + e] = r;
                g_qs[base + e] = 0.f;
                As[e * 136 + row] = tf32r(r);
                p = __fmaf_rn(r, r, p);
            }
        } else {
            #pragma unroll
            for (int j = 0; j < 16; j++) As[(j * 16 + l16) * 136 + row] = 0.f;
        }
        float sh = __shfl_xor_sync(0xffffffffu, p, 4);
        float q = __fadd_rn(p, sh);
        sh = __shfl_xor_sync(0xffffffffu, q, 8);
        float c = __fadd_rn(q, sh);
        sh = __shfl_xor_sync(0xffffffffu, c, 1);
        float u = __fadd_rn(c, sh);
        sh = __shfl_xor_sync(0xffffffffu, u, 2);
        float s = __fadd_rn(u, sh);
        if (l16 == 0) sE[row] = s;
    }
    __syncthreads();

    int br = tid >> 1, bk = (tid & 1) * 8;

    for (int s = 0; s < NQ_; s++) {
        const float* cb = cbs + (size_t)s * BINS_ * D_;
        const float* G = bnorm + s * BINS_;
        if (tid < 128) sBest[tid] = ~0ull;
        __syncthreads();

        unsigned long long bb0[4], bb1[4];
        #pragma unroll
        for (int mf = 0; mf < 4; mf++) { bb0[mf] = ~0ull; bb1[mf] = ~0ull; }

        for (int nt = 0; nt < BINS_ / 128; nt++) {
            float acc[4][4][4];
            #pragma unroll
            for (int a = 0; a < 4; a++)
                #pragma unroll
                for (int b = 0; b < 4; b++)
                    #pragma unroll
                    for (int q = 0; q < 4; q++) acc[a][b][q] = 0.f;

            const float* bptr = cb + (size_t)(nt * 128 + br) * D_;
            float4 pb0 = *(const float4*)(bptr + bk);
            float4 pb1 = *(const float4*)(bptr + bk + 4);
            Bs[(bk + 0) * 136 + br] = tf32r(pb0.x);
            Bs[(bk + 1) * 136 + br] = tf32r(pb0.y);
            Bs[(bk + 2) * 136 + br] = tf32r(pb0.z);
            Bs[(bk + 3) * 136 + br] = tf32r(pb0.w);
            Bs[(bk + 4) * 136 + br] = tf32r(pb1.x);
            Bs[(bk + 5) * 136 + br] = tf32r(pb1.y);
            Bs[(bk + 6) * 136 + br] = tf32r(pb1.z);
            Bs[(bk + 7) * 136 + br] = tf32r(pb1.w);
            __syncthreads();

            int buf = 0;
            for (int k0 = 0; k0 < D_; k0 += 16) {
                bool hn = (k0 + 16) < D_;
                if (hn) {
                    pb0 = *(const float4*)(bptr + k0 + 16 + bk);
                    pb1 = *(const float4*)(bptr + k0 + 16 + bk + 4);
                }
                #pragma unroll
                for (int g2 = 0; g2 < 2; g2++) {
                    int ka = k0 + t4 + g2 * 8, kc = k0 + t4 + 4 + g2 * 8;
                    int kba = (buf * 16 + t4 + g2 * 8), kbc = (buf * 16 + t4 + 4 + g2 * 8);
                    unsigned a[4][4], b[4][2];
                    #pragma unroll
                    for (int mf = 0; mf < 4; mf++) {
                        int mb = wm * 64 + mf * 16 + g;
                        a[mf][0] = __float_as_uint(As[ka * 136 + mb]);
                        a[mf][1] = __float_as_uint(As[ka * 136 + mb + 8]);
                        a[mf][2] = __float_as_uint(As[kc * 136 + mb]);
                        a[mf][3] = __float_as_uint(As[kc * 136 + mb + 8]);
                    }
                    #pragma unroll
                    for (int nf = 0; nf < 4; nf++) {
                        int nb = wn * 32 + nf * 8 + g;
                        b[nf][0] = __float_as_uint(Bs[kba * 136 + nb]);
                        b[nf][1] = __float_as_uint(Bs[kbc * 136 + nb]);
                    }
                    #pragma unroll
                    for (int mf = 0; mf < 4; mf++)
                        #pragma unroll
                        for (int nf = 0; nf < 4; nf++)
                            mma_tf32(acc[mf][nf], a[mf], b[nf]);
                }
                if (hn) {
                    int nb2 = buf ^ 1;
                    Bs[(nb2 * 16 + bk + 0) * 136 + br] = tf32r(pb0.x);
                    Bs[(nb2 * 16 + bk + 1) * 136 + br] = tf32r(pb0.y);
                    Bs[(nb2 * 16 + bk + 2) * 136 + br] = tf32r(pb0.z);
                    Bs[(nb2 * 16 + bk + 3) * 136 + br] = tf32r(pb0.w);
                    Bs[(nb2 * 16 + bk + 4) * 136 + br] = tf32r(pb1.x);
                    Bs[(nb2 * 16 + bk + 5) * 136 + br] = tf32r(pb1.y);
                    Bs[(nb2 * 16 + bk + 6) * 136 + br] = tf32r(pb1.z);
                    Bs[(nb2 * 16 + bk + 7) * 136 + br] = tf32r(pb1.w);
                }
                __syncthreads();
                buf ^= 1;
            }
            // fold dist into running per-row best
            #pragma unroll
            for (int mf = 0; mf < 4; mf++) {
                int lo0 = wm * 64 + mf * 16 + g, lo1 = lo0 + 8;
                float e0 = sE[lo0], e1 = sE[lo1];
                #pragma unroll
                for (int nf = 0; nf < 4; nf++) {
                    int col = nt * 128 + wn * 32 + nf * 8 + 2 * t4;
                    float gv0 = G[col], gv1 = G[col + 1];
                    float s00 = __fadd_rn(__fadd_rn(e0, -__fmul_rn(2.f, acc[mf][nf][0])), gv0);
                    float s01 = __fadd_rn(__fadd_rn(e0, -__fmul_rn(2.f, acc[mf][nf][1])), gv1);
                    float s10 = __fadd_rn(__fadd_rn(e1, -__fmul_rn(2.f, acc[mf][nf][2])), gv0);
                    float s11 = __fadd_rn(__fadd_rn(e1, -__fmul_rn(2.f, acc[mf][nf][3])), gv1);
                    unsigned long long p;
                    p = ((unsigned long long)f2key(s00) << 32) | (unsigned)col;
                    bb0[mf] = (p < bb0[mf]) ? p : bb0[mf];
                    p = ((unsigned long long)f2key(s01) << 32) | (unsigned)(col + 1);
                    bb0[mf] = (p < bb0[mf]) ? p : bb0[mf];
                    p = ((unsigned long long)f2key(s10) << 32) | (unsigned)col;
                    bb1[mf] = (p < bb1[mf]) ? p : bb1[mf];
                    p = ((unsigned long long)f2key(s11) << 32) | (unsigned)(col + 1);
                    bb1[mf] = (p < bb1[mf]) ? p : bb1[mf];
                }
            }
        }
        // reduce t4 lanes, publish to sBest
        #pragma unroll
        for (int mf = 0; mf < 4; mf++) {
            #pragma unroll
            for (int o = 1; o < 4; o <<= 1) {
                unsigned long long t0 = __shfl_xor_sync(0xffffffffu, bb0[mf], o);
                unsigned long long t1 = __shfl_xor_sync(0xffffffffu, bb1[mf], o);
                bb0[mf] = (t0 < bb0[mf]) ? t0 : bb0[mf];
                bb1[mf] = (t1 < bb1[mf]) ? t1 : bb1[mf];
            }
            if (t4 == 0) {
                atomicMin(&sBest[wm * 64 + mf * 16 + g], bb0[mf]);
                atomicMin(&sBest[wm * 64 + mf * 16 + g + 8], bb1[mf]);
            }
        }
        __syncthreads();
        // update: res -= q (exact, gmem), qs += q, re-round into As, new E
        for (int pass = 0; pass < 8; pass++) {
            int row = pass * 16 + r16;
            int m = m0 + row;
            float p = 0.f;
            if (m < M_) {
                int idx = (int)(sBest[row] & 0xffffffffu);
                const float* qrow = cb + (size_t)idx * D_;
                size_t base = (size_t)m * D_;
                #pragma unroll
                for (int j = 0; j < 16; j++) {
                    int e = j * 16 + l16;
                    float qv = __ldg(qrow + e);
                    float rs = g_res[base + e];
                    float qs = g_qs[base + e];
                    float nr = __fadd_rn(rs, -qv);
                    g_res[base + e] = nr;
                    g_qs[base + e] = __fadd_rn(qs, qv);
                    As[e * 136 + row] = tf32r(nr);
                    p = __fmaf_rn(nr, nr, p);
                }
            }
            float sh = __shfl_xor_sync(0xffffffffu, p, 4);
            float q = __fadd_rn(p, sh);
            sh = __shfl_xor_sync(0xffffffffu, q, 8);
            float c = __fadd_rn(q, sh);
            sh = __shfl_xor_sync(0xffffffffu, c, 1);
            float u = __fadd_rn(c, sh);
            sh = __shfl_xor_sync(0xffffffffu, u, 2);
            float sv = __fadd_rn(u, sh);
            if (l16 == 0) sE[row] = sv;
        }
        __syncthreads();
    }
    // denorm: den = (sen + (qs - sen)) * nrm
    for (int i = tid; i < 128 * D_; i += 256) {
        int row = i >> 8, e = i & 255;
        int m = m0 + row;
        if (m < M_) {
            size_t o = (size_t)m * D_ + e;
            float sen = g_sen[o], qs = g_qs[o], nv = g_nrm[o];
            float quant = __fadd_rn(sen, __fadd_rn(qs, -sen));
            g_den[o] = __fmul_rn(quant, nv);
        }
    }
}

static float* symf(const void* sym) {
    void* p = nullptr;
    cudaGetSymbolAddress(&p, sym);
    return (float*)p;
}

extern "C" void kernel_launch(void* const* d_in, const int* in_sizes, int n_in,
                              void* d_out, int out_size) {
    const float* feature  = (const float*)d_in[0];
    const float* centroid = (const float*)d_in[1];
    const float* enc_w0 = (const float*)d_in[2];  const float* enc_b0 = (const float*)d_in[3];
    const float* enc_w1 = (const float*)d_in[4];  const float* enc_b1 = (const float*)d_in[5];
    const float* enc_w2 = (const float*)d_in[6];  const float* enc_b2 = (const float*)d_in[7];
    const float* dec_w0 = (const float*)d_in[8];  const float* dec_b0 = (const float*)d_in[9];
    const float* dec_w1 = (const float*)d_in[10]; const float* dec_b1 = (const float*)d_in[11];
    const float* dec_w2 = (const float*)d_in[12]; const float* dec_b2 = (const float*)d_in[13];
    const float* nrm_w0 = (const float*)d_in[14]; const float* nrm_b0 = (const float*)d_in[15];
    const float* nrm_w1 = (const float*)d_in[16]; const float* nrm_b1 = (const float*)d_in[17];
    const float* nrm_w2 = (const float*)d_in[18]; const float* nrm_b2 = (const float*)d_in[19];
    const float* codebooks = (const float*)d_in[20];
    float* out = (float*)d_out;

    float* px   = symf(g_x);    float* plin = symf(g_lin);
    float* praw = symf(g_raw);  float* pobt = symf(g_obt);
    float* ph0  = symf(g_h0);   float* ph1  = symf(g_h1);
    float* ph0b = symf(g_h0b);  float* ph1b = symf(g_h1b);
    float* pspk = symf(g_spk);  float* pnrm = symf(g_nrm);
    float* pden = symf(g_den);
    float* pcn  = symf(g_cnorm); float* pbn = symf(g_bnorm);
    float* pE   = symf(g_E);
    void* pv = nullptr;
    cudaGetSymbolAddress(&pv, g_xb);  __nv_bfloat16* pxb = (__nv_bfloat16*)pv;
    cudaGetSymbolAddress(&pv, g_cb);  __nv_bfloat16* pcb = (__nv_bfloat16*)pv;

    static bool attr_done = false;
    if (!attr_done) {
        cudaFuncSetAttribute(rvq_all, cudaFuncAttributeMaxDynamicSharedMemorySize,
                             RVQ_SM_TOTAL);
        attr_done = true;
    }

    dim3 tb(32, 8);
    dim3 tg((T_ + 31) / 32, C_ / 32, B_);
    transpose_in<<<tg, tb>>>(feature, px, pxb);

    to_bf16<<<(KC_ * C_ / 2 + 255) / 256, 256>>>(centroid, pcb, KC_ * C_);

    row_sumsq_warp<<<(KC_ + 15) / 16, 256>>>(centroid, pcn, KC_, C_);
    row_sumsq_warp<<<(NQ_ * BINS_ + 15) / 16, 256>>>(codebooks, pbn, NQ_ * BINS_, D_);
    row_sumsq_warp<<<(M_ + 15) / 16, 256>>>(px, pE, M_, C_);

    reset_amin<<<(M_ + 255) / 256, 256>>>();
    {
        dim3 g(KC_ / 128, (M_ + 127) / 128);
        vq_approx<<<g, 256>>>(pxb, pcb, pcn);
    }
    vq_exact<<<(M_ + 7) / 8, 256>>>(centroid);

    dim3 gH2(H_ / 128, (M_ + 127) / 128, 2);
    dim3 gD2(D_ / 128, (M_ + 127) / 128, 2);
    gemm_tf32_dual<1, 2><<<gH2, 256>>>(praw, plin, enc_w0, nrm_w0, enc_b0, nrm_b0,
                                       ph0, ph0b, M_, H_, C_);
    gemm_tf32_dual<1, 2><<<gH2, 256>>>(ph0, ph0b, enc_w1, nrm_w1, enc_b1, nrm_b1,
                                       ph1, ph1b, M_, H_, H_);
    gemm_tf32_dual<0, 2><<<gD2, 256>>>(ph1, ph1b, enc_w2, nrm_w2, enc_b2, nrm_b2,
                                       pspk, pnrm, M_, D_, H_);

    // fused RVQ: init + 4 stages + denorm, one persistent launch
    rvq_all<<<(M_ + 127) / 128, 256, RVQ_SM_TOTAL>>>(codebooks, pbn);

    dim3 gHt(H_ / 128, (M_ + 127) / 128);
    dim3 gCt(C_ / 128, (M_ + 127) / 128);
    gemm_tf32<1, false><<<gHt, 256>>>(pden, dec_w0, dec_b0, nullptr, ph0, M_, H_, D_);
    gemm_tf32<1, false><<<gHt, 256>>>(ph0, dec_w1, dec_b1, nullptr, ph1, M_, H_, H_);
    gemm_tf32<0, true><<<gCt, 256>>>(ph1, dec_w2, dec_b2, plin, pobt, M_, C_, H_);

    transpose_out<<<tg, tb>>>(pobt, out);
}

// round 17
// speedup vs baseline: 1.0917x; 1.0917x over previous
#include <cuda_runtime.h>
#include <cuda_bf16.h>
#include <cstdint>

#define B_    8
#define C_    1024
#define T_    1500
#define M_    (B_*T_)
#define KC_   8192
#define D_    256
#define H_    512
#define NQ_   4
#define BINS_ 1024
#define LRELU_SLOPE 0.01f
#define EPS_  1e-8f
#define MARGIN_ 64.0f

__device__ __align__(16) float g_x   [M_*C_];
__device__ __align__(16) float g_lin [M_*C_];
__device__ __align__(16) float g_raw [M_*C_];
__device__ __align__(16) float g_obt [M_*C_];
__device__ __align__(16) float g_h0  [M_*H_];
__device__ __align__(16) float g_h1  [M_*H_];
__device__ __align__(16) float g_h0b [M_*H_];
__device__ __align__(16) float g_h1b [M_*H_];
__device__ __align__(16) float g_spk [M_*D_];
__device__ __align__(16) float g_nrm [M_*D_];
__device__ __align__(16) float g_sen [M_*D_];
__device__ __align__(16) float g_res [M_*D_];
__device__ __align__(16) float g_qs  [M_*D_];
__device__ __align__(16) float g_den [M_*D_];
__device__ float g_cnorm[KC_];
__device__ float g_bnorm[NQ_*BINS_];
__device__ float g_E[M_];
__device__ unsigned long long g_mk[M_];
__device__ __align__(16) __nv_bfloat16 g_xb[M_*C_];
__device__ __align__(16) __nv_bfloat16 g_cb[KC_*C_];
__device__ __align__(16) __nv_bfloat16 g_adist[(size_t)M_*KC_];
__device__ unsigned int g_amin[M_];

__device__ __forceinline__ unsigned int f2key(float f) {
    unsigned int u = __float_as_uint(f);
    return (u & 0x80000000u) ? ~u : (u | 0x80000000u);
}
__device__ __forceinline__ float key2f(unsigned int u) {
    return (u & 0x80000000u) ? __uint_as_float(u ^ 0x80000000u)
                             : __uint_as_float(~u);
}
__device__ __forceinline__ float tf32r(float v) {
    unsigned u;
    asm("cvt.rna.tf32.f32 %0, %1;" : "=r"(u) : "f"(v));
    return __uint_as_float(u);
}

__device__ __forceinline__ void mma16816(float* c, const unsigned* a, const unsigned* b) {
    asm volatile(
        "mma.sync.aligned.m16n8k16.row.col.f32.bf16.bf16.f32 "
        "{%0,%1,%2,%3}, {%4,%5,%6,%7}, {%8,%9}, {%0,%1,%2,%3};\n"
        : "+f"(c[0]), "+f"(c[1]), "+f"(c[2]), "+f"(c[3])
        : "r"(a[0]), "r"(a[1]), "r"(a[2]), "r"(a[3]), "r"(b[0]), "r"(b[1]));
}
__device__ __forceinline__ void mma_tf32(float* c, const unsigned* a, const unsigned* b) {
    asm volatile(
        "mma.sync.aligned.m16n8k8.row.col.f32.tf32.tf32.f32 "
        "{%0,%1,%2,%3}, {%4,%5,%6,%7}, {%8,%9}, {%0,%1,%2,%3};\n"
        : "+f"(c[0]), "+f"(c[1]), "+f"(c[2]), "+f"(c[3])
        : "r"(a[0]), "r"(a[1]), "r"(a[2]), "r"(a[3]), "r"(b[0]), "r"(b[1]));
}
__device__ __forceinline__ void ldsm_x4(unsigned& r0, unsigned& r1,
                                        unsigned& r2, unsigned& r3, unsigned addr) {
    asm volatile("ldmatrix.sync.aligned.m8n8.x4.shared.b16 {%0,%1,%2,%3}, [%4];"
                 : "=r"(r0), "=r"(r1), "=r"(r2), "=r"(r3) : "r"(addr));
}

// ---- coalesced row sum-of-squares (optionally resets amin) ----------------
__global__ void row_sumsq_warp(const float* __restrict__ rows, float* __restrict__ out,
                               unsigned int* amin, int R, int L) {
    int w = (blockIdx.x * blockDim.x + threadIdx.x) >> 5;
    int lane = threadIdx.x & 31;
    int half = lane >> 4, l = lane & 15;
    int r = w * 2 + half;
    float p = 0.f;
    if (r < R) {
        const float* base = rows + (size_t)r * L + l;
        for (int j = 0; j < L; j += 16) {
            float v = __ldg(base + j);
            p = __fmaf_rn(v, v, p);
        }
    }
    float t = __shfl_xor_sync(0xffffffffu, p, 4);
    float q = __fadd_rn(p, t);
    t = __shfl_xor_sync(0xffffffffu, q, 8);
    float c = __fadd_rn(q, t);
    t = __shfl_xor_sync(0xffffffffu, c, 1);
    float u = __fadd_rn(c, t);
    t = __shfl_xor_sync(0xffffffffu, u, 2);
    float s = __fadd_rn(u, t);
    if (l == 0 && r < R) {
        out[r] = s;
        if (amin) amin[r] = 0xFFFFFFFFu;
    }
}

__global__ void to_bf16(const float* __restrict__ in, __nv_bfloat16* __restrict__ out,
                        int n) {
    int i = blockIdx.x * blockDim.x + threadIdx.x;
    if (i * 2 + 1 < n) {
        float2 v = ((const float2*)in)[i];
        ((__nv_bfloat162*)out)[i] = __nv_bfloat162(__float2bfloat16(v.x),
                                                   __float2bfloat16(v.y));
    }
}

// fused: (B,C,T)->(B*T,C) transpose + bf16 copy of x
__global__ void transpose_in(const float* __restrict__ f, float* __restrict__ x,
                             __nv_bfloat16* __restrict__ xb) {
    __shared__ float tile[32][33];
    int b = blockIdx.z, t0 = blockIdx.x * 32, c0 = blockIdx.y * 32;
    int tx = threadIdx.x, ty = threadIdx.y;
    #pragma unroll
    for (int i = 0; i < 32; i += 8) {
        int cc = c0 + ty + i, t = t0 + tx;
        if (t < T_ && cc < C_) tile[ty + i][tx] = f[((size_t)b * C_ + cc) * T_ + t];
    }
    __syncthreads();
    #pragma unroll
    for (int i = 0; i < 32; i += 8) {
        int tt = t0 + ty + i, cc = c0 + tx;
        if (tt < T_ && cc < C_) {
            float v = tile[tx][ty + i];
            size_t o = ((size_t)b * T_ + tt) * C_ + cc;
            x[o] = v;
            xb[o] = __float2bfloat16(v);
        }
    }
}

__global__ void transpose_out(const float* __restrict__ x, float* __restrict__ f) {
    __shared__ float tile[32][33];
    int b = blockIdx.z, t0 = blockIdx.x * 32, c0 = blockIdx.y * 32;
    int tx = threadIdx.x, ty = threadIdx.y;
    #pragma unroll
    for (int i = 0; i < 32; i += 8) {
        int tt = t0 + ty + i, cc = c0 + tx;
        if (tt < T_ && cc < C_) tile[ty + i][tx] = x[((size_t)b * T_ + tt) * C_ + cc];
    }
    __syncthreads();
    #pragma unroll
    for (int i = 0; i < 32; i += 8) {
        int cc = c0 + ty + i, t = t0 + tx;
        if (t < T_ && cc < C_) f[((size_t)b * C_ + cc) * T_ + t] = tile[tx][ty + i];
    }
}

// ---- PASS 1: bf16 mma.sync approx distances (linguistic) ------------------
__global__ __launch_bounds__(256)
void vq_approx(const __nv_bfloat16* __restrict__ xb,
               const __nv_bfloat16* __restrict__ cb,
               const float* __restrict__ G) {
    __shared__ __nv_bfloat16 a_sm[2][128][40];
    __shared__ __nv_bfloat16 b_sm[2][128][40];
    const unsigned PITCHB = 80, BUFB = 128 * 80;
    int tid = threadIdx.x;
    int m0 = blockIdx.y * 128, n0 = blockIdx.x * 128;
    int w = tid >> 5, lane = tid & 31;
    int wm = w & 1, wn = w >> 1;
    float acc[4][4][4];
    #pragma unroll
    for (int a = 0; a < 4; a++)
        #pragma unroll
        for (int b = 0; b < 4; b++)
            #pragma unroll
            for (int q = 0; q < 4; q++) acc[a][b][q] = 0.f;

    unsigned aBase = (unsigned)__cvta_generic_to_shared(&a_sm[0][0][0]);
    unsigned bBase = (unsigned)__cvta_generic_to_shared(&b_sm[0][0][0]);
    int i8 = lane & 7, tt = lane >> 3;
    unsigned aRow = (tt & 1) * 8 + i8, aCol = (tt >> 1) * 16;
    unsigned bRow = (tt >> 1) * 8 + i8, bCol = (tt & 1) * 16;

    int row0 = tid >> 2, cg0 = tid & 3;
    int row1 = (tid + 256) >> 2, cg1 = tid & 3;
    int gm0 = m0 + row0, gm1 = m0 + row1;

    float4 pa0 = make_float4(0.f,0.f,0.f,0.f), pa1 = make_float4(0.f,0.f,0.f,0.f);
    float4 pb0, pb1;
    if (gm0 < M_) pa0 = *(const float4*)(xb + (size_t)gm0 * C_ + cg0 * 8);
    if (gm1 < M_) pa1 = *(const float4*)(xb + (size_t)gm1 * C_ + cg1 * 8);
    pb0 = *(const float4*)(cb + (size_t)(n0 + row0) * C_ + cg0 * 8);
    pb1 = *(const float4*)(cb + (size_t)(n0 + row1) * C_ + cg1 * 8);
    *(float4*)&a_sm[0][row0][cg0 * 8] = pa0;
    *(float4*)&a_sm[0][row1][cg1 * 8] = pa1;
    *(float4*)&b_sm[0][row0][cg0 * 8] = pb0;
    *(float4*)&b_sm[0][row1][cg1 * 8] = pb1;
    __syncthreads();

    int buf = 0;
    for (int k0 = 0; k0 < C_; k0 += 32) {
        bool hn = (k0 + 32) < C_;
        if (hn) {
            int kn = k0 + 32;
            pa0 = make_float4(0.f,0.f,0.f,0.f); pa1 = make_float4(0.f,0.f,0.f,0.f);
            if (gm0 < M_) pa0 = *(const float4*)(xb + (size_t)gm0 * C_ + kn + cg0 * 8);
            if (gm1 < M_) pa1 = *(const float4*)(xb + (size_t)gm1 * C_ + kn + cg1 * 8);
            pb0 = *(const float4*)(cb + (size_t)(n0 + row0) * C_ + kn + cg0 * 8);
            pb1 = *(const float4*)(cb + (size_t)(n0 + row1) * C_ + kn + cg1 * 8);
        }
        unsigned bufOff = buf * BUFB;
        #pragma unroll
        for (int kk = 0; kk < 32; kk += 16) {
            unsigned a[4][4], b[4][2];
            #pragma unroll
            for (int mf = 0; mf < 4; mf++) {
                unsigned ad = aBase + bufOff +
                              (unsigned)(wm * 64 + mf * 16 + aRow) * PITCHB + aCol + kk * 2;
                ldsm_x4(a[mf][0], a[mf][1], a[mf][2], a[mf][3], ad);
            }
            #pragma unroll
            for (int p = 0; p < 2; p++) {
                unsigned bd = bBase + bufOff +
                              (unsigned)(wn * 32 + p * 16 + bRow) * PITCHB + bCol + kk * 2;
                unsigned r0, r1, r2, r3;
                ldsm_x4(r0, r1, r2, r3, bd);
                b[2 * p][0] = r0; b[2 * p][1] = r1;
                b[2 * p + 1][0] = r2; b[2 * p + 1][1] = r3;
            }
            #pragma unroll
            for (int mf = 0; mf < 4; mf++)
                #pragma unroll
                for (int nf = 0; nf < 4; nf++)
                    mma16816(acc[mf][nf], a[mf], b[nf]);
        }
        if (hn) {
            int nb = buf ^ 1;
            *(float4*)&a_sm[nb][row0][cg0 * 8] = pa0;
            *(float4*)&a_sm[nb][row1][cg1 * 8] = pa1;
            *(float4*)&b_sm[nb][row0][cg0 * 8] = pb0;
            *(float4*)&b_sm[nb][row1][cg1 * 8] = pb1;
        }
        __syncthreads();
        buf ^= 1;
    }
    int r = lane >> 2, c2 = (lane & 3) * 2;
    #pragma unroll
    for (int mf = 0; mf < 4; mf++) {
        int ro0 = m0 + wm * 64 + mf * 16 + r;
        int ro1 = ro0 + 8;
        float mn0 = 3.4e38f, mn1 = 3.4e38f;
        #pragma unroll
        for (int nf = 0; nf < 4; nf++) {
            int col = n0 + wn * 32 + nf * 8 + c2;
            float gv0 = G[col], gv1 = G[col + 1];
            __nv_bfloat16 h00 = __float2bfloat16(gv0 - 2.f * acc[mf][nf][0]);
            __nv_bfloat16 h01 = __float2bfloat16(gv1 - 2.f * acc[mf][nf][1]);
            __nv_bfloat16 h10 = __float2bfloat16(gv0 - 2.f * acc[mf][nf][2]);
            __nv_bfloat16 h11 = __float2bfloat16(gv1 - 2.f * acc[mf][nf][3]);
            if (ro0 < M_)
                *(__nv_bfloat162*)&g_adist[(size_t)ro0 * KC_ + col] = __nv_bfloat162(h00, h01);
            if (ro1 < M_)
                *(__nv_bfloat162*)&g_adist[(size_t)ro1 * KC_ + col] = __nv_bfloat162(h10, h11);
            mn0 = fminf(mn0, fminf(__bfloat162float(h00), __bfloat162float(h01)));
            mn1 = fminf(mn1, fminf(__bfloat162float(h10), __bfloat162float(h11)));
        }
        #pragma unroll
        for (int o = 1; o < 4; o <<= 1) {
            mn0 = fminf(mn0, __shfl_xor_sync(0xffffffffu, mn0, o));
            mn1 = fminf(mn1, __shfl_xor_sync(0xffffffffu, mn1, o));
        }
        if ((lane & 3) == 0) {
            if (ro0 < M_) atomicMin(&g_amin[ro0], f2key(mn0));
            if (ro1 < M_) atomicMin(&g_amin[ro1], f2key(mn1));
        }
    }
}

// ---- PASS 2: exact re-evaluation of candidates + fused gather/sub ---------
__global__ __launch_bounds__(256)
void vq_exact(const float* __restrict__ cent) {
    __shared__ float xs[8][1024];
    __shared__ int cands[8][256];
    __shared__ int cnt[8];
    int w = threadIdx.x >> 5, lane = threadIdx.x & 31;
    int m0 = blockIdx.x * 8;
    #pragma unroll
    for (int r = 0; r < 8; r++) {
        int m = m0 + r;
        if (m < M_)
            ((float4*)xs[r])[threadIdx.x] = ((const float4*)(g_x + (size_t)m * C_))[threadIdx.x];
    }
    if (lane == 0) cnt[w] = 0;
    __syncthreads();
    int m = m0 + w;
    if (m >= M_) return;
    float thr = key2f(g_amin[m]) + MARGIN_;
    const __nv_bfloat16* drow = g_adist + (size_t)m * KC_;
    for (int base = 0; base < KC_; base += 256) {
        int n0c = base + lane * 8;
        uint4 vv = *(const uint4*)(drow + n0c);
        const __nv_bfloat162* hp = (const __nv_bfloat162*)&vv;
        #pragma unroll
        for (int q = 0; q < 4; q++) {
            if (__bfloat162float(hp[q].x) <= thr) {
                int p = atomicAdd(&cnt[w], 1);
                if (p < 256) cands[w][p] = n0c + q * 2;
            }
            if (__bfloat162float(hp[q].y) <= thr) {
                int p = atomicAdd(&cnt[w], 1);
                if (p < 256) cands[w][p] = n0c + q * 2 + 1;
            }
        }
    }
    __syncwarp();
    int nc = cnt[w]; if (nc > 256) nc = 256;
    float E = g_E[m];
    unsigned long long best = ~0ull;
    for (int base = 0; base < nc; base += 32) {
        int li = base + lane;
        unsigned long long pk = ~0ull;
        if (li < nc) {
            int n = cands[w][li];
            const float* c = cent + (size_t)n * C_;
            float F = 0.f;
            for (int k = 0; k < C_; k += 4) {
                float4 cv = __ldg((const float4*)(c + k));
                F = __fmaf_rn(xs[w][k],     cv.x, F);
                F = __fmaf_rn(xs[w][k + 1], cv.y, F);
                F = __fmaf_rn(xs[w][k + 2], cv.z, F);
                F = __fmaf_rn(xs[w][k + 3], cv.w, F);
            }
            float t1 = __fmul_rn(2.0f, F);
            float t2 = __fadd_rn(E, -t1);
            float s  = __fadd_rn(t2, g_cnorm[n]);
            pk = ((unsigned long long)f2key(s) << 32) | (unsigned)n;
        }
        #pragma unroll
        for (int o = 16; o; o >>= 1) {
            unsigned long long ot = __shfl_xor_sync(0xffffffffu, pk, o);
            pk = ot < pk ? ot : pk;
        }
        best = pk < best ? pk : best;
    }
    if (lane == 0) g_mk[m] = best;
    int idx = (int)(best & 0xffffffffu);
    const float* crow = cent + (size_t)idx * C_;
    for (int k = lane * 4; k < C_; k += 128) {
        float4 cv = __ldg((const float4*)(crow + k));
        float4 xv = *(const float4*)&xs[w][k];
        *(float4*)(g_lin + (size_t)m * C_ + k) = cv;
        float4 rv = make_float4(__fadd_rn(xv.x, -cv.x), __fadd_rn(xv.y, -cv.y),
                                __fadd_rn(xv.z, -cv.z), __fadd_rn(xv.w, -cv.w));
        *(float4*)(g_raw + (size_t)m * C_ + k) = rv;
    }
}

// ---- TF32 GEMM + bias + act (+ add), BK=16 --------------------------------
template <int ACT, bool ADD>
__global__ __launch_bounds__(256)
void gemm_tf32(const float* __restrict__ A, const float* __restrict__ W,
               const float* __restrict__ bias, const float* __restrict__ addin,
               float* __restrict__ Cp, int M, int N, int K) {
    __shared__ float As[2][16][136];
    __shared__ float Ws[2][16][136];
    int tid = threadIdx.x;
    int m0 = blockIdx.y * 128, n0 = blockIdx.x * 128;
    int w = tid >> 5, lane = tid & 31;
    int wm = w & 1, wn = w >> 1;
    int g = lane >> 2, t4 = lane & 3;
    int lr = tid >> 1, kb = (tid & 1) * 8;
    int wk = tid >> 4, wnl = (tid & 15) * 8;
    int gm = m0 + lr;
    float acc[4][4][4];
    #pragma unroll
    for (int a = 0; a < 4; a++)
        #pragma unroll
        for (int b = 0; b < 4; b++)
            #pragma unroll
            for (int q = 0; q < 4; q++) acc[a][b][q] = 0.f;

    float4 pa0 = make_float4(0.f,0.f,0.f,0.f), pa1 = pa0;
    if (gm < M) {
        pa0 = *(const float4*)(A + (size_t)gm * K + kb);
        pa1 = *(const float4*)(A + (size_t)gm * K + kb + 4);
    }
    float4 pw0 = *(const float4*)(W + (size_t)wk * N + n0 + wnl);
    float4 pw1 = *(const float4*)(W + (size_t)wk * N + n0 + wnl + 4);
    As[0][kb][lr] = tf32r(pa0.x); As[0][kb+1][lr] = tf32r(pa0.y);
    As[0][kb+2][lr] = tf32r(pa0.z); As[0][kb+3][lr] = tf32r(pa0.w);
    As[0][kb+4][lr] = tf32r(pa1.x); As[0][kb+5][lr] = tf32r(pa1.y);
    As[0][kb+6][lr] = tf32r(pa1.z); As[0][kb+7][lr] = tf32r(pa1.w);
    Ws[0][wk][wnl] = tf32r(pw0.x); Ws[0][wk][wnl+1] = tf32r(pw0.y);
    Ws[0][wk][wnl+2] = tf32r(pw0.z); Ws[0][wk][wnl+3] = tf32r(pw0.w);
    Ws[0][wk][wnl+4] = tf32r(pw1.x); Ws[0][wk][wnl+5] = tf32r(pw1.y);
    Ws[0][wk][wnl+6] = tf32r(pw1.z); Ws[0][wk][wnl+7] = tf32r(pw1.w);
    __syncthreads();

    int buf = 0;
    for (int k0 = 0; k0 < K; k0 += 16) {
        bool hn = (k0 + 16) < K;
        if (hn) {
            int kn = k0 + 16;
            pa0 = make_float4(0.f,0.f,0.f,0.f); pa1 = pa0;
            if (gm < M) {
                pa0 = *(const float4*)(A + (size_t)gm * K + kn + kb);
                pa1 = *(const float4*)(A + (size_t)gm * K + kn + kb + 4);
            }
            pw0 = *(const float4*)(W + (size_t)(kn + wk) * N + n0 + wnl);
            pw1 = *(const float4*)(W + (size_t)(kn + wk) * N + n0 + wnl + 4);
        }
        #pragma unroll
        for (int g2 = 0; g2 < 2; g2++) {
            int ka = t4 + g2 * 8, kc = t4 + 4 + g2 * 8;
            unsigned a[4][4], b[4][2];
            #pragma unroll
            for (int mf = 0; mf < 4; mf++) {
                int mb = wm * 64 + mf * 16 + g;
                a[mf][0] = __float_as_uint(As[buf][ka][mb]);
                a[mf][1] = __float_as_uint(As[buf][ka][mb + 8]);
                a[mf][2] = __float_as_uint(As[buf][kc][mb]);
                a[mf][3] = __float_as_uint(As[buf][kc][mb + 8]);
            }
            #pragma unroll
            for (int nf = 0; nf < 4; nf++) {
                int nb = wn * 32 + nf * 8 + g;
                b[nf][0] = __float_as_uint(Ws[buf][ka][nb]);
                b[nf][1] = __float_as_uint(Ws[buf][kc][nb]);
            }
            #pragma unroll
            for (int mf = 0; mf < 4; mf++)
                #pragma unroll
                for (int nf = 0; nf < 4; nf++)
                    mma_tf32(acc[mf][nf], a[mf], b[nf]);
        }
        if (hn) {
            int nb2 = buf ^ 1;
            As[nb2][kb][lr] = tf32r(pa0.x); As[nb2][kb+1][lr] = tf32r(pa0.y);
            As[nb2][kb+2][lr] = tf32r(pa0.z); As[nb2][kb+3][lr] = tf32r(pa0.w);
            As[nb2][kb+4][lr] = tf32r(pa1.x); As[nb2][kb+5][lr] = tf32r(pa1.y);
            As[nb2][kb+6][lr] = tf32r(pa1.z); As[nb2][kb+7][lr] = tf32r(pa1.w);
            Ws[nb2][wk][wnl] = tf32r(pw0.x); Ws[nb2][wk][wnl+1] = tf32r(pw0.y);
            Ws[nb2][wk][wnl+2] = tf32r(pw0.z); Ws[nb2][wk][wnl+3] = tf32r(pw0.w);
            Ws[nb2][wk][wnl+4] = tf32r(pw1.x); Ws[nb2][wk][wnl+5] = tf32r(pw1.y);
            Ws[nb2][wk][wnl+6] = tf32r(pw1.z); Ws[nb2][wk][wnl+7] = tf32r(pw1.w);
        }
        __syncthreads();
        buf ^= 1;
    }
    #pragma unroll
    for (int mf = 0; mf < 4; mf++) {
        int ro0 = m0 + wm * 64 + mf * 16 + g;
        int ro1 = ro0 + 8;
        #pragma unroll
        for (int nf = 0; nf < 4; nf++) {
            int col = n0 + wn * 32 + nf * 8 + 2 * t4;
            float b0 = bias[col], b1 = bias[col + 1];
            float v00 = acc[mf][nf][0] + b0, v01 = acc[mf][nf][1] + b1;
            float v10 = acc[mf][nf][2] + b0, v11 = acc[mf][nf][3] + b1;
            if (ACT == 1) {
                v00 = (v00 >= 0.f) ? v00 : LRELU_SLOPE * v00;
                v01 = (v01 >= 0.f) ? v01 : LRELU_SLOPE * v01;
                v10 = (v10 >= 0.f) ? v10 : LRELU_SLOPE * v10;
                v11 = (v11 >= 0.f) ? v11 : LRELU_SLOPE * v11;
            } else if (ACT == 2) {
                v00 = fmaxf(v00, 0.f); v01 = fmaxf(v01, 0.f);
                v10 = fmaxf(v10, 0.f); v11 = fmaxf(v11, 0.f);
            }
            if (ro0 < M) {
                float2 o = make_float2(v00, v01);
                if (ADD) {
                    float2 ad = *(const float2*)(addin + (size_t)ro0 * N + col);
                    o.x += ad.x; o.y += ad.y;
                }
                *(float2*)(Cp + (size_t)ro0 * N + col) = o;
            }
            if (ro1 < M) {
                float2 o = make_float2(v10, v11);
                if (ADD) {
                    float2 ad = *(const float2*)(addin + (size_t)ro1 * N + col);
                    o.x += ad.x; o.y += ad.y;
                }
                *(float2*)(Cp + (size_t)ro1 * N + col) = o;
            }
        }
    }
}

// ---- dual-chain TF32 GEMM (enc || nrm), BK=16 -----------------------------
template <int ACTA, int ACTB>
__global__ __launch_bounds__(256)
void gemm_tf32_dual(const float* __restrict__ A0, const float* __restrict__ A1,
                    const float* __restrict__ W0, const float* __restrict__ W1,
                    const float* __restrict__ b0, const float* __restrict__ b1,
                    float* __restrict__ C0, float* __restrict__ C1,
                    int M, int N, int K) {
    const float* A = blockIdx.z ? A1 : A0;
    const float* W = blockIdx.z ? W1 : W0;
    const float* bias = blockIdx.z ? b1 : b0;
    float* Cp = blockIdx.z ? C1 : C0;
    __shared__ float As[2][16][136];
    __shared__ float Ws[2][16][136];
    int tid = threadIdx.x;
    int m0 = blockIdx.y * 128, n0 = blockIdx.x * 128;
    int w = tid >> 5, lane = tid & 31;
    int wm = w & 1, wn = w >> 1;
    int g = lane >> 2, t4 = lane & 3;
    int lr = tid >> 1, kb = (tid & 1) * 8;
    int wk = tid >> 4, wnl = (tid & 15) * 8;
    int gm = m0 + lr;
    float acc[4][4][4];
    #pragma unroll
    for (int a = 0; a < 4; a++)
        #pragma unroll
        for (int b = 0; b < 4; b++)
            #pragma unroll
            for (int q = 0; q < 4; q++) acc[a][b][q] = 0.f;

    float4 pa0 = make_float4(0.f,0.f,0.f,0.f), pa1 = pa0;
    if (gm < M) {
        pa0 = *(const float4*)(A + (size_t)gm * K + kb);
        pa1 = *(const float4*)(A + (size_t)gm * K + kb + 4);
    }
    float4 pw0 = *(const float4*)(W + (size_t)wk * N + n0 + wnl);
    float4 pw1 = *(const float4*)(W + (size_t)wk * N + n0 + wnl + 4);
    As[0][kb][lr] = tf32r(pa0.x); As[0][kb+1][lr] = tf32r(pa0.y);
    As[0][kb+2][lr] = tf32r(pa0.z); As[0][kb+3][lr] = tf32r(pa0.w);
    As[0][kb+4][lr] = tf32r(pa1.x); As[0][kb+5][lr] = tf32r(pa1.y);
    As[0][kb+6][lr] = tf32r(pa1.z); As[0][kb+7][lr] = tf32r(pa1.w);
    Ws[0][wk][wnl] = tf32r(pw0.x); Ws[0][wk][wnl+1] = tf32r(pw0.y);
    Ws[0][wk][wnl+2] = tf32r(pw0.z); Ws[0][wk][wnl+3] = tf32r(pw0.w);
    Ws[0][wk][wnl+4] = tf32r(pw1.x); Ws[0][wk][wnl+5] = tf32r(pw1.y);
    Ws[0][wk][wnl+6] = tf32r(pw1.z); Ws[0][wk][wnl+7] = tf32r(pw1.w);
    __syncthreads();

    int buf = 0;
    for (int k0 = 0; k0 < K; k0 += 16) {
        bool hn = (k0 + 16) < K;
        if (hn) {
            int kn = k0 + 16;
            pa0 = make_float4(0.f,0.f,0.f,0.f); pa1 = pa0;
            if (gm < M) {
                pa0 = *(const float4*)(A + (size_t)gm * K + kn + kb);
                pa1 = *(const float4*)(A + (size_t)gm * K + kn + kb + 4);
            }
            pw0 = *(const float4*)(W + (size_t)(kn + wk) * N + n0 + wnl);
            pw1 = *(const float4*)(W + (size_t)(kn + wk) * N + n0 + wnl + 4);
        }
        #pragma unroll
        for (int g2 = 0; g2 < 2; g2++) {
            int ka = t4 + g2 * 8, kc = t4 + 4 + g2 * 8;
            unsigned a[4][4], b[4][2];
            #pragma unroll
            for (int mf = 0; mf < 4; mf++) {
                int mb = wm * 64 + mf * 16 + g;
                a[mf][0] = __float_as_uint(As[buf][ka][mb]);
                a[mf][1] = __float_as_uint(As[buf][ka][mb + 8]);
                a[mf][2] = __float_as_uint(As[buf][kc][mb]);
                a[mf][3] = __float_as_uint(As[buf][kc][mb + 8]);
            }
            #pragma unroll
            for (int nf = 0; nf < 4; nf++) {
                int nb = wn * 32 + nf * 8 + g;
                b[nf][0] = __float_as_uint(Ws[buf][ka][nb]);
                b[nf][1] = __float_as_uint(Ws[buf][kc][nb]);
            }
            #pragma unroll
            for (int mf = 0; mf < 4; mf++)
                #pragma unroll
                for (int nf = 0; nf < 4; nf++)
                    mma_tf32(acc[mf][nf], a[mf], b[nf]);
        }
        if (hn) {
            int nb2 = buf ^ 1;
            As[nb2][kb][lr] = tf32r(pa0.x); As[nb2][kb+1][lr] = tf32r(pa0.y);
            As[nb2][kb+2][lr] = tf32r(pa0.z); As[nb2][kb+3][lr] = tf32r(pa0.w);
            As[nb2][kb+4][lr] = tf32r(pa1.x); As[nb2][kb+5][lr] = tf32r(pa1.y);
            As[nb2][kb+6][lr] = tf32r(pa1.z); As[nb2][kb+7][lr] = tf32r(pa1.w);
            Ws[nb2][wk][wnl] = tf32r(pw0.x); Ws[nb2][wk][wnl+1] = tf32r(pw0.y);
            Ws[nb2][wk][wnl+2] = tf32r(pw0.z); Ws[nb2][wk][wnl+3] = tf32r(pw0.w);
            Ws[nb2][wk][wnl+4] = tf32r(pw1.x); Ws[nb2][wk][wnl+5] = tf32r(pw1.y);
            Ws[nb2][wk][wnl+6] = tf32r(pw1.z); Ws[nb2][wk][wnl+7] = tf32r(pw1.w);
        }
        __syncthreads();
        buf ^= 1;
    }
    int ACT = blockIdx.z ? ACTB : ACTA;
    #pragma unroll
    for (int mf = 0; mf < 4; mf++) {
        int ro0 = m0 + wm * 64 + mf * 16 + g;
        int ro1 = ro0 + 8;
        #pragma unroll
        for (int nf = 0; nf < 4; nf++) {
            int col = n0 + wn * 32 + nf * 8 + 2 * t4;
            float b0 = bias[col], b1 = bias[col + 1];
            float v00 = acc[mf][nf][0] + b0, v01 = acc[mf][nf][1] + b1;
            float v10 = acc[mf][nf][2] + b0, v11 = acc[mf][nf][3] + b1;
            if (ACT == 1) {
                v00 = (v00 >= 0.f) ? v00 : LRELU_SLOPE * v00;
                v01 = (v01 >= 0.f) ? v01 : LRELU_SLOPE * v01;
                v10 = (v10 >= 0.f) ? v10 : LRELU_SLOPE * v10;
                v11 = (v11 >= 0.f) ? v11 : LRELU_SLOPE * v11;
            } else if (ACT == 2) {
                v00 = fmaxf(v00, 0.f); v01 = fmaxf(v01, 0.f);
                v10 = fmaxf(v10, 0.f); v11 = fmaxf(v11, 0.f);
            }
            if (ro0 < M) *(float2*)(Cp + (size_t)ro0 * N + col) = make_float2(v00, v01);
            if (ro1 < M) *(float2*)(Cp + (size_t)ro1 * N + col) = make_float2(v10, v11);
        }
    }
}

// ---- TF32 GEMM + argmin (RVQ), BK=16 --------------------------------------
__global__ __launch_bounds__(256)
void gemm_argmin_tf32(const float* __restrict__ A, const float* __restrict__ Bm,
                      const float* __restrict__ G, const float* __restrict__ E,
                      unsigned long long* __restrict__ mk, int M, int N, int K) {
    __shared__ float As[2][16][136];
    __shared__ float Bs[2][16][136];
    int tid = threadIdx.x;
    int m0 = blockIdx.y * 128, n0 = blockIdx.x * 128;
    int w = tid >> 5, lane = tid & 31;
    int wm = w & 1, wn = w >> 1;
    int g = lane >> 2, t4 = lane & 3;
    int lr = tid >> 1, kb = (tid & 1) * 8;
    int gm = m0 + lr;
    float acc[4][4][4];
    #pragma unroll
    for (int a = 0; a < 4; a++)
        #pragma unroll
        for (int b = 0; b < 4; b++)
            #pragma unroll
            for (int q = 0; q < 4; q++) acc[a][b][q] = 0.f;

    float4 pa0 = make_float4(0.f,0.f,0.f,0.f), pa1 = pa0;
    if (gm < M) {
        pa0 = *(const float4*)(A + (size_t)gm * K + kb);
        pa1 = *(const float4*)(A + (size_t)gm * K + kb + 4);
    }
    float4 pb0 = *(const float4*)(Bm + (size_t)(n0 + lr) * K + kb);
    float4 pb1 = *(const float4*)(Bm + (size_t)(n0 + lr) * K + kb + 4);
    As[0][kb][lr] = tf32r(pa0.x); As[0][kb+1][lr] = tf32r(pa0.y);
    As[0][kb+2][lr] = tf32r(pa0.z); As[0][kb+3][lr] = tf32r(pa0.w);
    As[0][kb+4][lr] = tf32r(pa1.x); As[0][kb+5][lr] = tf32r(pa1.y);
    As[0][kb+6][lr] = tf32r(pa1.z); As[0][kb+7][lr] = tf32r(pa1.w);
    Bs[0][kb][lr] = tf32r(pb0.x); Bs[0][kb+1][lr] = tf32r(pb0.y);
    Bs[0][kb+2][lr] = tf32r(pb0.z); Bs[0][kb+3][lr] = tf32r(pb0.w);
    Bs[0][kb+4][lr] = tf32r(pb1.x); Bs[0][kb+5][lr] = tf32r(pb1.y);
    Bs[0][kb+6][lr] = tf32r(pb1.z); Bs[0][kb+7][lr] = tf32r(pb1.w);
    __syncthreads();

    int buf = 0;
    for (int k0 = 0; k0 < K; k0 += 16) {
        bool hn = (k0 + 16) < K;
        if (hn) {
            int kn = k0 + 16;
            pa0 = make_float4(0.f,0.f,0.f,0.f); pa1 = pa0;
            if (gm < M) {
                pa0 = *(const float4*)(A + (size_t)gm * K + kn + kb);
                pa1 = *(const float4*)(A + (size_t)gm * K + kn + kb + 4);
            }
            pb0 = *(const float4*)(Bm + (size_t)(n0 + lr) * K + kn + kb);
            pb1 = *(const float4*)(Bm + (size_t)(n0 + lr) * K + kn + kb + 4);
        }
        #pragma unroll
        for (int g2 = 0; g2 < 2; g2++) {
            int ka = t4 + g2 * 8, kc = t4 + 4 + g2 * 8;
            unsigned a[4][4], b[4][2];
            #pragma unroll
            for (int mf = 0; mf < 4; mf++) {
                int mb = wm * 64 + mf * 16 + g;
                a[mf][0] = __float_as_uint(As[buf][ka][mb]);
                a[mf][1] = __float_as_uint(As[buf][ka][mb + 8]);
                a[mf][2] = __float_as_uint(As[buf][kc][mb]);
                a[mf][3] = __float_as_uint(As[buf][kc][mb + 8]);
            }
            #pragma unroll
            for (int nf = 0; nf < 4; nf++) {
                int nb = wn * 32 + nf * 8 + g;
                b[nf][0] = __float_as_uint(Bs[buf][ka][nb]);
                b[nf][1] = __float_as_uint(Bs[buf][kc][nb]);
            }
            #pragma unroll
            for (int mf = 0; mf < 4; mf++)
                #pragma unroll
                for (int nf = 0; nf < 4; nf++)
                    mma_tf32(acc[mf][nf], a[mf], b[nf]);
        }
        if (hn) {
            int nb2 = buf ^ 1;
            As[nb2][kb][lr] = tf32r(pa0.x); As[nb2][kb+1][lr] = tf32r(pa0.y);
            As[nb2][kb+2][lr] = tf32r(pa0.z); As[nb2][kb+3][lr] = tf32r(pa0.w);
            As[nb2][kb+4][lr] = tf32r(pa1.x); As[nb2][kb+5][lr] = tf32r(pa1.y);
            As[nb2][kb+6][lr] = tf32r(pa1.z); As[nb2][kb+7][lr] = tf32r(pa1.w);
            Bs[nb2][kb][lr] = tf32r(pb0.x); Bs[nb2][kb+1][lr] = tf32r(pb0.y);
            Bs[nb2][kb+2][lr] = tf32r(pb0.z); Bs[nb2][kb+3][lr] = tf32r(pb0.w);
            Bs[nb2][kb+4][lr] = tf32r(pb1.x); Bs[nb2][kb+5][lr] = tf32r(pb1.y);
            Bs[nb2][kb+6][lr] = tf32r(pb1.z); Bs[nb2][kb+7][lr] = tf32r(pb1.w);
        }
        __syncthreads();
        buf ^= 1;
    }
    #pragma unroll
    for (int mf = 0; mf < 4; mf++) {
        int ro0 = m0 + wm * 64 + mf * 16 + g;
        int ro1 = ro0 + 8;
        float e0 = (ro0 < M) ? E[ro0] : 0.f;
        float e1 = (ro1 < M) ? E[ro1] : 0.f;
        unsigned long long bb0 = ~0ull, bb1 = ~0ull;
        #pragma unroll
        for (int nf = 0; nf < 4; nf++) {
            int col = n0 + wn * 32 + nf * 8 + 2 * t4;
            float gv0 = G[col], gv1 = G[col + 1];
            float s00 = __fadd_rn(__fadd_rn(e0, -__fmul_rn(2.f, acc[mf][nf][0])), gv0);
            float s01 = __fadd_rn(__fadd_rn(e0, -__fmul_rn(2.f, acc[mf][nf][1])), gv1);
            float s10 = __fadd_rn(__fadd_rn(e1, -__fmul_rn(2.f, acc[mf][nf][2])), gv0);
            float s11 = __fadd_rn(__fadd_rn(e1, -__fmul_rn(2.f, acc[mf][nf][3])), gv1);
            unsigned long long p;
            p = ((unsigned long long)f2key(s00) << 32) | (unsigned)col;
            bb0 = (p < bb0) ? p : bb0;
            p = ((unsigned long long)f2key(s01) << 32) | (unsigned)(col + 1);
            bb0 = (p < bb0) ? p : bb0;
            p = ((unsigned long long)f2key(s10) << 32) | (unsigned)col;
            bb1 = (p < bb1) ? p : bb1;
            p = ((unsigned long long)f2key(s11) << 32) | (unsigned)(col + 1);
            bb1 = (p < bb1) ? p : bb1;
        }
        #pragma unroll
        for (int o = 1; o < 4; o <<= 1) {
            unsigned long long t0 = __shfl_xor_sync(0xffffffffu, bb0, o);
            unsigned long long t1 = __shfl_xor_sync(0xffffffffu, bb1, o);
            bb0 = (t0 < bb0) ? t0 : bb0;
            bb1 = (t1 < bb1) ? t1 : bb1;
        }
        if (t4 == 0) {
            if (ro0 < M) atomicMin(&mk[ro0], bb0);
            if (ro1 < M) atomicMin(&mk[ro1], bb1);
        }
    }
}

// ---- fused: sen = spk/(nrm+eps); res=sen; qs=0; E=sumsq(res); mk=~0 -------
__global__ void norm_init_fuse() {
    int t = blockIdx.x * blockDim.x + threadIdx.x;
    int m = t >> 4, l = t & 15;
    if (m >= M_) return;
    size_t base = (size_t)m * D_;
    float p = 0.f;
    #pragma unroll
    for (int j = 0; j < D_ / 16; j++) {
        int e = j * 16 + l;
        float se = g_spk[base + e], nv = g_nrm[base + e];
        float r = __fdiv_rn(se, __fadd_rn(nv, EPS_));
        g_sen[base + e] = r;
        g_res[base + e] = r;
        g_qs[base + e] = 0.f;
        p = __fmaf_rn(r, r, p);
    }
    float sh = __shfl_xor_sync(0xffffffffu, p, 4);
    float q = __fadd_rn(p, sh);
    sh = __shfl_xor_sync(0xffffffffu, q, 8);
    float c = __fadd_rn(q, sh);
    sh = __shfl_xor_sync(0xffffffffu, c, 1);
    float u = __fadd_rn(c, sh);
    sh = __shfl_xor_sync(0xffffffffu, u, 2);
    float s = __fadd_rn(u, sh);
    if (l == 0) { g_E[m] = s; g_mk[m] = ~0ull; }
}

// ---- fused RVQ stage update ----------------------------------------------
__global__ void rvq_fuse(const float* __restrict__ cb) {
    int t = blockIdx.x * blockDim.x + threadIdx.x;
    int m = t >> 4, l = t & 15;
    if (m >= M_) return;
    size_t base = (size_t)m * D_;
    int idx = (int)(g_mk[m] & 0xffffffffu);
    const float* qrow = cb + (size_t)idx * D_;
    float p = 0.f;
    #pragma unroll
    for (int j = 0; j < D_ / 16; j++) {
        int e = j * 16 + l;
        float qv = __ldg(qrow + e);
        float rs = g_res[base + e];
        float qs = g_qs[base + e];
        float nr = __fadd_rn(rs, -qv);
        g_res[base + e] = nr;
        g_qs[base + e] = __fadd_rn(qs, qv);
        p = __fmaf_rn(nr, nr, p);
    }
    float sh = __shfl_xor_sync(0xffffffffu, p, 4);
    float q = __fadd_rn(p, sh);
    sh = __shfl_xor_sync(0xffffffffu, q, 8);
    float c = __fadd_rn(q, sh);
    sh = __shfl_xor_sync(0xffffffffu, c, 1);
    float u = __fadd_rn(c, sh);
    sh = __shfl_xor_sync(0xffffffffu, u, 2);
    float s = __fadd_rn(u, sh);
    if (l == 0) { g_E[m] = s; g_mk[m] = ~0ull; }
}

__global__ void denorm_mul() {
    int i = blockIdx.x * blockDim.x + threadIdx.x;
    if (i >= M_ * D_) return;
    float sen = g_sen[i], qs = g_qs[i], nv = g_nrm[i];
    float quant = __fadd_rn(sen, __fadd_rn(qs, -sen));
    g_den[i] = __fmul_rn(quant, nv);
}

static float* symf(const void* sym) {
    void* p = nullptr;
    cudaGetSymbolAddress(&p, sym);
    return (float*)p;
}

extern "C" void kernel_launch(void* const* d_in, const int* in_sizes, int n_in,
                              void* d_out, int out_size) {
    const float* feature  = (const float*)d_in[0];
    const float* centroid = (const float*)d_in[1];
    const float* enc_w0 = (const float*)d_in[2];  const float* enc_b0 = (const float*)d_in[3];
    const float* enc_w1 = (const float*)d_in[4];  const float* enc_b1 = (const float*)d_in[5];
    const float* enc_w2 = (const float*)d_in[6];  const float* enc_b2 = (const float*)d_in[7];
    const float* dec_w0 = (const float*)d_in[8];  const float* dec_b0 = (const float*)d_in[9];
    const float* dec_w1 = (const float*)d_in[10]; const float* dec_b1 = (const float*)d_in[11];
    const float* dec_w2 = (const float*)d_in[12]; const float* dec_b2 = (const float*)d_in[13];
    const float* nrm_w0 = (const float*)d_in[14]; const float* nrm_b0 = (const float*)d_in[15];
    const float* nrm_w1 = (const float*)d_in[16]; const float* nrm_b1 = (const float*)d_in[17];
    const float* nrm_w2 = (const float*)d_in[18]; const float* nrm_b2 = (const float*)d_in[19];
    const float* codebooks = (const float*)d_in[20];
    float* out = (float*)d_out;

    float* px   = symf(g_x);    float* plin = symf(g_lin);
    float* praw = symf(g_raw);  float* pobt = symf(g_obt);
    float* ph0  = symf(g_h0);   float* ph1  = symf(g_h1);
    float* ph0b = symf(g_h0b);  float* ph1b = symf(g_h1b);
    float* pspk = symf(g_spk);  float* pnrm = symf(g_nrm);
    float* pres = symf(g_res);  float* pden = symf(g_den);
    float* pcn  = symf(g_cnorm); float* pbn = symf(g_bnorm);
    float* pE   = symf(g_E);
    void* pmkv = nullptr; cudaGetSymbolAddress(&pmkv, g_mk);
    unsigned long long* pmk = (unsigned long long*)pmkv;
    void* pav = nullptr; cudaGetSymbolAddress(&pav, g_amin);
    unsigned int* pam = (unsigned int*)pav;
    void* pv = nullptr;
    cudaGetSymbolAddress(&pv, g_xb);  __nv_bfloat16* pxb = (__nv_bfloat16*)pv;
    cudaGetSymbolAddress(&pv, g_cb);  __nv_bfloat16* pcb = (__nv_bfloat16*)pv;

    dim3 tb(32, 8);
    dim3 tg((T_ + 31) / 32, C_ / 32, B_);
    transpose_in<<<tg, tb>>>(feature, px, pxb);

    to_bf16<<<(KC_ * C_ / 2 + 255) / 256, 256>>>(centroid, pcb, KC_ * C_);

    row_sumsq_warp<<<(KC_ + 15) / 16, 256>>>(centroid, pcn, nullptr, KC_, C_);
    row_sumsq_warp<<<(NQ_ * BINS_ + 15) / 16, 256>>>(codebooks, pbn, nullptr, NQ_ * BINS_, D_);
    row_sumsq_warp<<<(M_ + 15) / 16, 256>>>(px, pE, pam, M_, C_);

    {
        dim3 g(KC_ / 128, (M_ + 127) / 128);
        vq_approx<<<g, 256>>>(pxb, pcb, pcn);
    }
    vq_exact<<<(M_ + 7) / 8, 256>>>(centroid);

    dim3 gH2(H_ / 128, (M_ + 127) / 128, 2);
    dim3 gD2(D_ / 128, (M_ + 127) / 128, 2);
    gemm_tf32_dual<1, 2><<<gH2, 256>>>(praw, plin, enc_w0, nrm_w0, enc_b0, nrm_b0,
                                       ph0, ph0b, M_, H_, C_);
    gemm_tf32_dual<1, 2><<<gH2, 256>>>(ph0, ph0b, enc_w1, nrm_w1, enc_b1, nrm_b1,
                                       ph1, ph1b, M_, H_, H_);
    gemm_tf32_dual<0, 2><<<gD2, 256>>>(ph1, ph1b, enc_w2, nrm_w2, enc_b2, nrm_b2,
                                       pspk, pnrm, M_, D_, H_);

    norm_init_fuse<<<(M_ * 16 + 255) / 256, 256>>>();

    for (int s = 0; s < NQ_; s++) {
        dim3 g(BINS_ / 128, (M_ + 127) / 128);
        gemm_argmin_tf32<<<g, 256>>>(pres, codebooks + (size_t)s * BINS_ * D_,
                                     pbn + s * BINS_, pE, pmk, M_, BINS_, D_);
        rvq_fuse<<<(M_ * 16 + 255) / 256, 256>>>(codebooks + (size_t)s * BINS_ * D_);
    }

    denorm_mul<<<(M_ * D_ + 255) / 256, 256>>>();

    dim3 gHt(H_ / 128, (M_ + 127) / 128);
    dim3 gCt(C_ / 128, (M_ + 127) / 128);
    gemm_tf32<1, false><<<gHt, 256>>>(pden, dec_w0, dec_b0, nullptr, ph0, M_, H_, D_);
    gemm_tf32<1, false><<<gHt, 256>>>(ph0, dec_w1, dec_b1, nullptr, ph1, M_, H_, H_);
    gemm_tf32<0, true><<<gCt, 256>>>(ph1, dec_w2, dec_b2, plin, pobt, M_, C_, H_);

    transpose_out<<<tg, tb>>>(pobt, out);
}